// round 1
// baseline (speedup 1.0000x reference)
#include <cuda_runtime.h>

#define B_   8
#define D_   512
#define L_   4096
#define T_   8192
#define KS   17

// ---------------- scratch (device globals: allocation-free) ----------------
__device__ float g_Gt[3][D_][D_];       // folded weights, [k][c][e]  (3 MB)
__device__ float g_cb[D_];              // projected conv bias
__device__ float g_z[(size_t)B_ * D_ * T_];  // intermediate z (134 MB)

// ---------------- f32x2 packed helpers ----------------
__device__ __forceinline__ unsigned long long pack2(float lo, float hi) {
    unsigned long long r;
    asm("mov.b64 %0, {%1, %2};" : "=l"(r) : "f"(lo), "f"(hi));
    return r;
}
__device__ __forceinline__ unsigned long long fma2(unsigned long long a,
                                                   unsigned long long b,
                                                   unsigned long long c) {
    unsigned long long d;
    asm("fma.rn.f32x2 %0, %1, %2, %3;" : "=l"(d) : "l"(a), "l"(b), "l"(c));
    return d;
}
__device__ __forceinline__ float2 unpack2(unsigned long long v) {
    float2 f;
    asm("mov.b64 {%0, %1}, %2;" : "=f"(f.x), "=f"(f.y) : "l"(v));
    return f;
}

// ---------------- kernel 1: fold weights  Gt[k][c][e] = sum_d P[e,d] W[d,c,k] ----
__global__ __launch_bounds__(256) void fold_kernel(const float* __restrict__ conv_w,
                                                   const float* __restrict__ proj_w) {
    __shared__ float sP[32][33];      // [e'][d']
    __shared__ float sW[3][32][33];   // [k][d'][c']
    const int c0 = blockIdx.x * 32;
    const int e0 = blockIdx.y * 32;
    const int t  = threadIdx.x;

    const int ld  = t & 31;   // load lane (d' for P, c' for W)
    const int lr  = t >> 5;   // load row base (8 rows/pass)

    const int el  = t & 31;         // compute: e'
    const int cb4 = (t >> 5) << 2;  // compute: 4 c-values

    float acc[3][4];
#pragma unroll
    for (int k = 0; k < 3; k++)
#pragma unroll
        for (int j = 0; j < 4; j++) acc[k][j] = 0.f;

    for (int d0 = 0; d0 < D_; d0 += 32) {
#pragma unroll
        for (int p = 0; p < 4; p++) {
            int r = lr + p * 8;
            sP[r][ld] = proj_w[(size_t)(e0 + r) * D_ + d0 + ld];
#pragma unroll
            for (int k = 0; k < 3; k++)
                sW[k][r][ld] = conv_w[(size_t)(d0 + r) * (D_ * 3) + (size_t)(c0 + ld) * 3 + k];
        }
        __syncthreads();
#pragma unroll
        for (int dd = 0; dd < 32; dd++) {
            float pv = sP[el][dd];
#pragma unroll
            for (int j = 0; j < 4; j++) {
#pragma unroll
                for (int k = 0; k < 3; k++)
                    acc[k][j] += sW[k][dd][cb4 + j] * pv;
            }
        }
        __syncthreads();
    }
#pragma unroll
    for (int k = 0; k < 3; k++)
#pragma unroll
        for (int j = 0; j < 4; j++)
            g_Gt[k][c0 + cb4 + j][e0 + el] = acc[k][j];
}

// ---------------- kernel 2: projected conv bias ----------------
__global__ __launch_bounds__(256) void cb_kernel(const float* __restrict__ proj_w,
                                                 const float* __restrict__ conv_b) {
    int e = blockIdx.x * 256 + threadIdx.x;
    if (e >= D_) return;
    float s = 0.f;
    const float* row = proj_w + (size_t)e * D_;
#pragma unroll 8
    for (int d = 0; d < D_; d++) s += row[d] * conv_b[d];
    g_cb[e] = s;
}

// ---------------- kernel 3: fused upsample GEMM -----------------------------
// z[b,e,2i]   = sum_c G1[c,e] x[b,c,i]                         + cb[e]
// z[b,e,2i+1] = sum_c G0[c,e] x[b,c,i] + G2[c,e] x[b,c,i+1]    + cb[e]
#define TM 64
#define TN 64
#define KC 32
__global__ __launch_bounds__(256) void upgemm_kernel(const float* __restrict__ x) {
    __shared__ float sW[3][KC][TM];   // [k][c'][e']
    __shared__ float sX[KC][72];      // [c'][i'], 65 used

    const int i0 = blockIdx.x * TN;
    const int e0 = blockIdx.y * TM;
    const int b  = blockIdx.z;
    const int t  = threadIdx.x;
    const int tx = t & 15;            // i group (4 outputs)
    const int ty = t >> 4;            // e group (4 outputs)

    unsigned long long accE[4][2], accO[4][2];
#pragma unroll
    for (int i = 0; i < 4; i++) {
        accE[i][0] = 0ull; accE[i][1] = 0ull;
        accO[i][0] = 0ull; accO[i][1] = 0ull;
    }

    const float* xb = x + (size_t)b * D_ * L_;

    for (int c0 = 0; c0 < D_; c0 += KC) {
        // weights: 3 * 32 rows * 64 e  (1536 float4, 6 per thread)
#pragma unroll
        for (int p = 0; p < 6; p++) {
            int idx = p * 256 + t;
            int k   = idx >> 9;
            int rem = idx & 511;
            int cc  = rem >> 4;
            int e4  = (rem & 15) << 2;
            float4 v = *(const float4*)&g_Gt[k][c0 + cc][e0 + e4];
            *(float4*)&sW[k][cc][e4] = v;
        }
        // x: 32 rows * 64 i (512 float4, 2 per thread) + 1 halo column
#pragma unroll
        for (int p = 0; p < 2; p++) {
            int idx = p * 256 + t;
            int cc  = idx >> 4;
            int i4  = (idx & 15) << 2;
            float4 v = *(const float4*)&xb[(size_t)(c0 + cc) * L_ + i0 + i4];
            *(float4*)&sX[cc][i4] = v;
        }
        if (t < 32) {
            int ii = i0 + TN;
            sX[t][TN] = (ii < L_) ? xb[(size_t)(c0 + t) * L_ + ii] : 0.f;
        }
        __syncthreads();

#pragma unroll
        for (int k = 0; k < KC; k++) {
            ulonglong2 w0 = *(const ulonglong2*)&sW[0][k][ty * 4];
            ulonglong2 w1 = *(const ulonglong2*)&sW[1][k][ty * 4];
            ulonglong2 w2 = *(const ulonglong2*)&sW[2][k][ty * 4];
            float4 xv = *(const float4*)&sX[k][tx * 4];
            float  xn = sX[k][tx * 4 + 4];

            unsigned long long xp0 = pack2(xv.x, xv.x);
            unsigned long long xp1 = pack2(xv.y, xv.y);
            unsigned long long xp2 = pack2(xv.z, xv.z);
            unsigned long long xp3 = pack2(xv.w, xv.w);
            unsigned long long xp4 = pack2(xn,   xn);

            // even phase: W1 * x[i]
            accE[0][0] = fma2(w1.x, xp0, accE[0][0]); accE[0][1] = fma2(w1.y, xp0, accE[0][1]);
            accE[1][0] = fma2(w1.x, xp1, accE[1][0]); accE[1][1] = fma2(w1.y, xp1, accE[1][1]);
            accE[2][0] = fma2(w1.x, xp2, accE[2][0]); accE[2][1] = fma2(w1.y, xp2, accE[2][1]);
            accE[3][0] = fma2(w1.x, xp3, accE[3][0]); accE[3][1] = fma2(w1.y, xp3, accE[3][1]);
            // odd phase: W0 * x[i] + W2 * x[i+1]
            accO[0][0] = fma2(w0.x, xp0, accO[0][0]); accO[0][1] = fma2(w0.y, xp0, accO[0][1]);
            accO[1][0] = fma2(w0.x, xp1, accO[1][0]); accO[1][1] = fma2(w0.y, xp1, accO[1][1]);
            accO[2][0] = fma2(w0.x, xp2, accO[2][0]); accO[2][1] = fma2(w0.y, xp2, accO[2][1]);
            accO[3][0] = fma2(w0.x, xp3, accO[3][0]); accO[3][1] = fma2(w0.y, xp3, accO[3][1]);
            accO[0][0] = fma2(w2.x, xp1, accO[0][0]); accO[0][1] = fma2(w2.y, xp1, accO[0][1]);
            accO[1][0] = fma2(w2.x, xp2, accO[1][0]); accO[1][1] = fma2(w2.y, xp2, accO[1][1]);
            accO[2][0] = fma2(w2.x, xp3, accO[2][0]); accO[2][1] = fma2(w2.y, xp3, accO[2][1]);
            accO[3][0] = fma2(w2.x, xp4, accO[3][0]); accO[3][1] = fma2(w2.y, xp4, accO[3][1]);
        }
        __syncthreads();
    }

    // epilogue: interleave even/odd into z, add projected conv bias
    float cbv[4];
#pragma unroll
    for (int eo = 0; eo < 4; eo++) cbv[eo] = g_cb[e0 + ty * 4 + eo];

#pragma unroll
    for (int ep = 0; ep < 2; ep++) {
        float2 E[4], O[4];
#pragma unroll
        for (int i = 0; i < 4; i++) { E[i] = unpack2(accE[i][ep]); O[i] = unpack2(accO[i][ep]); }
#pragma unroll
        for (int h = 0; h < 2; h++) {
            int eo = ep * 2 + h;
            float c = cbv[eo];
            float4 v0, v1;
            v0.x = (h ? E[0].y : E[0].x) + c;  v0.y = (h ? O[0].y : O[0].x) + c;
            v0.z = (h ? E[1].y : E[1].x) + c;  v0.w = (h ? O[1].y : O[1].x) + c;
            v1.x = (h ? E[2].y : E[2].x) + c;  v1.y = (h ? O[2].y : O[2].x) + c;
            v1.z = (h ? E[3].y : E[3].x) + c;  v1.w = (h ? O[3].y : O[3].x) + c;
            float* p = g_z + ((size_t)b * D_ + (e0 + ty * 4 + eo)) * T_ + 2 * (i0 + tx * 4);
            ((float4*)p)[0] = v0;
            ((float4*)p)[1] = v1;
        }
    }
}

// ---------------- kernel 4: depthwise 17-tap AA + output bias ----------------
#define CHUNK 1024
__global__ __launch_bounds__(256) void aa_kernel(const float* __restrict__ aa,
                                                 const float* __restrict__ pb,
                                                 float* __restrict__ out) {
    __shared__ float s[CHUNK + 16];
    const int row = blockIdx.y;            // b*512 + e
    const int c0  = blockIdx.x * CHUNK;
    const int t   = threadIdx.x;
    const float* zr = g_z + (size_t)row * T_;

    for (int idx = t; idx < CHUNK + 16; idx += 256) {
        int g = c0 - 8 + idx;
        s[idx] = (g >= 0 && g < T_) ? zr[g] : 0.f;
    }

    float kc[KS];
#pragma unroll
    for (int j = 0; j < KS; j++) kc[j] = __ldg(&aa[j]);
    float bias = __ldg(&pb[row & (D_ - 1)]);
    __syncthreads();

    const int o = t * 4;
    float w[20];
#pragma unroll
    for (int q = 0; q < 5; q++) {
        float4 v = *(const float4*)&s[o + q * 4];
        w[q * 4 + 0] = v.x; w[q * 4 + 1] = v.y; w[q * 4 + 2] = v.z; w[q * 4 + 3] = v.w;
    }

    float4 r;
    float acc0 = bias, acc1 = bias, acc2 = bias, acc3 = bias;
#pragma unroll
    for (int j = 0; j < KS; j++) {
        acc0 += kc[j] * w[j + 0];
        acc1 += kc[j] * w[j + 1];
        acc2 += kc[j] * w[j + 2];
        acc3 += kc[j] * w[j + 3];
    }
    r.x = acc0; r.y = acc1; r.z = acc2; r.w = acc3;
    *(float4*)&out[(size_t)row * T_ + c0 + o] = r;
}

// ---------------- launch ----------------
extern "C" void kernel_launch(void* const* d_in, const int* in_sizes, int n_in,
                              void* d_out, int out_size) {
    const float* x       = (const float*)d_in[0];
    const float* conv_w  = (const float*)d_in[1];
    const float* conv_b  = (const float*)d_in[2];
    const float* aa_k    = (const float*)d_in[3];
    const float* proj_w  = (const float*)d_in[4];
    const float* proj_b  = (const float*)d_in[5];
    float* out = (float*)d_out;

    fold_kernel<<<dim3(D_ / 32, D_ / 32), 256>>>(conv_w, proj_w);
    cb_kernel<<<dim3((D_ + 255) / 256), 256>>>(proj_w, conv_b);
    upgemm_kernel<<<dim3(L_ / TN, D_ / TM, B_), 256>>>(x);
    aa_kernel<<<dim3(T_ / CHUNK, B_ * D_), 256>>>(aa_k, proj_b, out);
}

// round 3
// speedup vs baseline: 1.3662x; 1.3662x over previous
#include <cuda_runtime.h>
#include <cuda_bf16.h>
#include <cstdint>

#define B_   8
#define D_   512
#define L_   4096
#define LP_  4097
#define T_   8192
#define KS   17

// ---------------- device scratch ----------------
__device__ __nv_bfloat16 g_Ahi[3][D_][D_];     // folded weights hi [k][e][c]
__device__ __nv_bfloat16 g_Alo[3][D_][D_];     // folded weights lo
__device__ __nv_bfloat16 g_Xhi[B_][LP_][D_];   // transposed x hi [b][i][c], row L zeroed
__device__ __nv_bfloat16 g_Xlo[B_][LP_][D_];
__device__ float g_cb[D_];                      // projected conv bias
__device__ float g_z[(size_t)B_ * D_ * T_];     // intermediate (134 MB)

// ---------------- PTX helpers (sm_80-era: valid at compute_103 PTX target) ----
__device__ __forceinline__ uint32_t smem_u32(const void* p) {
    uint32_t a;
    asm("{ .reg .u64 t; cvta.to.shared.u64 t, %1; cvt.u32.u64 %0, t; }" : "=r"(a) : "l"(p));
    return a;
}
__device__ __forceinline__ void cp16(uint32_t dst, const void* src) {
    asm volatile("cp.async.cg.shared.global [%0], [%1], 16;" :: "r"(dst), "l"(src));
}
#define CP_COMMIT()  asm volatile("cp.async.commit_group;" ::: "memory")
#define CP_WAIT1()   asm volatile("cp.async.wait_group 1;" ::: "memory")
#define CP_WAIT0()   asm volatile("cp.async.wait_group 0;" ::: "memory")

__device__ __forceinline__ void ldsm_x4(uint32_t* r, uint32_t addr) {
    asm volatile("ldmatrix.sync.aligned.m8n8.x4.shared.b16 {%0,%1,%2,%3}, [%4];"
                 : "=r"(r[0]), "=r"(r[1]), "=r"(r[2]), "=r"(r[3]) : "r"(addr));
}
__device__ __forceinline__ void mma_bf16(float* d, const uint32_t* a, const uint32_t* b) {
    asm volatile("mma.sync.aligned.m16n8k16.row.col.f32.bf16.bf16.f32 "
                 "{%0,%1,%2,%3}, {%4,%5,%6,%7}, {%8,%9}, {%0,%1,%2,%3};"
                 : "+f"(d[0]), "+f"(d[1]), "+f"(d[2]), "+f"(d[3])
                 : "r"(a[0]), "r"(a[1]), "r"(a[2]), "r"(a[3]), "r"(b[0]), "r"(b[1]));
}

// ---------------- kernel 1: fold weights + bf16 split ----------------
__global__ __launch_bounds__(256) void fold_kernel(const float* __restrict__ conv_w,
                                                   const float* __restrict__ proj_w) {
    __shared__ float sP[32][33];
    __shared__ float sW[3][32][33];
    const int c0 = blockIdx.x * 32;
    const int e0 = blockIdx.y * 32;
    const int t  = threadIdx.x;
    const int ld = t & 31, lr = t >> 5;
    const int el = t & 31, cb4 = (t >> 5) << 2;

    float acc[3][4];
#pragma unroll
    for (int k = 0; k < 3; k++)
#pragma unroll
        for (int j = 0; j < 4; j++) acc[k][j] = 0.f;

    for (int d0 = 0; d0 < D_; d0 += 32) {
#pragma unroll
        for (int p = 0; p < 4; p++) {
            int r = lr + p * 8;
            sP[r][ld] = proj_w[(size_t)(e0 + r) * D_ + d0 + ld];
#pragma unroll
            for (int k = 0; k < 3; k++)
                sW[k][r][ld] = conv_w[(size_t)(d0 + r) * (D_ * 3) + (size_t)(c0 + ld) * 3 + k];
        }
        __syncthreads();
#pragma unroll
        for (int dd = 0; dd < 32; dd++) {
            float pv = sP[el][dd];
#pragma unroll
            for (int j = 0; j < 4; j++)
#pragma unroll
                for (int k = 0; k < 3; k++)
                    acc[k][j] += sW[k][dd][cb4 + j] * pv;
        }
        __syncthreads();
    }
#pragma unroll
    for (int k = 0; k < 3; k++)
#pragma unroll
        for (int j = 0; j < 4; j++) {
            float v = acc[k][j];
            __nv_bfloat16 h = __float2bfloat16(v);
            __nv_bfloat16 l = __float2bfloat16(v - __bfloat162float(h));
            g_Ahi[k][e0 + el][c0 + cb4 + j] = h;
            g_Alo[k][e0 + el][c0 + cb4 + j] = l;
        }
}

// ---------------- kernel 2: projected conv bias ----------------
__global__ __launch_bounds__(256) void cb_kernel(const float* __restrict__ proj_w,
                                                 const float* __restrict__ conv_b) {
    int e = blockIdx.x * 256 + threadIdx.x;
    if (e >= D_) return;
    float s = 0.f;
    const float* row = proj_w + (size_t)e * D_;
#pragma unroll 8
    for (int d = 0; d < D_; d++) s += row[d] * conv_b[d];
    g_cb[e] = s;
}

// ---------------- kernel 3: transpose + bf16 split of x ----------------
__global__ __launch_bounds__(256) void xprep_kernel(const float* __restrict__ x) {
    __shared__ float s[32][33];
    const int i0 = blockIdx.x * 32, c0 = blockIdx.y * 32, b = blockIdx.z;
    const int t = threadIdx.x, li = t & 31, lr = t >> 5;
#pragma unroll
    for (int p = 0; p < 4; p++) {
        int c = lr + p * 8;
        s[c][li] = x[((size_t)b * D_ + (c0 + c)) * L_ + i0 + li];
    }
    __syncthreads();
#pragma unroll
    for (int p = 0; p < 4; p++) {
        int i = lr + p * 8;
        float v = s[li][i];
        __nv_bfloat16 h = __float2bfloat16(v);
        __nv_bfloat16 l = __float2bfloat16(v - __bfloat162float(h));
        g_Xhi[b][i0 + i][c0 + li] = h;
        g_Xlo[b][i0 + i][c0 + li] = l;
    }
}

__global__ __launch_bounds__(256) void zerox_kernel() {
    int idx = blockIdx.x * 256 + threadIdx.x;   // 8*512 = 4096
    int b = idx >> 9, c = idx & 511;
    g_Xhi[b][L_][c] = __float2bfloat16(0.f);
    g_Xlo[b][L_][c] = __float2bfloat16(0.f);
}

// ---------------- kernel 4: HMMA split-bf16 GEMM ----------------
// CTA tile: 128 e x 64 i.  K chunks of 32, double-buffered cp.async.
// smem rows of 80B (64B data + 16B pad) -> conflict-free ldmatrix.
#define KC      32
#define NCH     (D_ / KC)          // 16 chunks
#define A_ROWB  80
#define A_PLANE (128 * A_ROWB)     // 10240
#define A_SIZE  (6 * A_PLANE)      // 61440
#define X_PLANE (72 * A_ROWB)      // 5760 (65 rows used)
#define X_SIZE  (2 * X_PLANE)      // 11520
#define STAGE   (A_SIZE + X_SIZE)  // 72960
#define GEMM_SMEM (2 * STAGE)      // 145920

__device__ __forceinline__ void load_stage(uint32_t sb, int st, int ch,
                                           int e0, int i0, int b, int t) {
    const int c0 = ch * KC;
    const uint32_t base = sb + (uint32_t)st * STAGE;
    // A: 6 planes x 128 rows x 4 chunks of 16B = 3072 ops (12/thread)
#pragma unroll
    for (int p = 0; p < 12; p++) {
        int idx = p * 256 + t;
        int plane = idx >> 9;         // 0..5 = s*2+h
        int rem = idx & 511;
        int row = rem >> 2, cb = rem & 3;
        int s = plane >> 1, h = plane & 1;
        const __nv_bfloat16* src = (h ? &g_Alo[s][0][0] : &g_Ahi[s][0][0])
                                   + (size_t)(e0 + row) * D_ + c0 + cb * 8;
        cp16(base + plane * A_PLANE + row * A_ROWB + cb * 16, src);
    }
    // X: 2 halves x 65 rows x 4 chunks = 520 ops
    for (int idx = t; idx < 520; idx += 256) {
        int h = (idx >= 260);
        int rem = idx - h * 260;
        int row = rem >> 2, cb = rem & 3;
        const __nv_bfloat16* src = (h ? &g_Xlo[b][0][0] : &g_Xhi[b][0][0])
                                   + (size_t)(i0 + row) * D_ + c0 + cb * 8;
        cp16(base + A_SIZE + h * X_PLANE + row * A_ROWB + cb * 16, src);
    }
}

__global__ void __launch_bounds__(256, 1) gemm_kernel() {
    extern __shared__ char smem[];
    const uint32_t sb = smem_u32(smem);
    const int t = threadIdx.x, wid = t >> 5, lane = t & 31;
    const int i0 = blockIdx.x * 64, e0 = blockIdx.y * 128, b = blockIdx.z;
    const int e_w = (wid & 3) * 32;   // warp e offset within CTA
    const int i_w = (wid >> 2) * 32;  // warp i offset within CTA

    float accE[2][4][4], accO[2][4][4];
#pragma unroll
    for (int mt = 0; mt < 2; mt++)
#pragma unroll
        for (int nt = 0; nt < 4; nt++)
#pragma unroll
            for (int j = 0; j < 4; j++) { accE[mt][nt][j] = 0.f; accO[mt][nt][j] = 0.f; }

    load_stage(sb, 0, 0, e0, i0, b, t);
    CP_COMMIT();

    for (int ch = 0; ch < NCH; ++ch) {
        if (ch + 1 < NCH) {
            load_stage(sb, (ch + 1) & 1, ch + 1, e0, i0, b, t);
            CP_COMMIT();
            CP_WAIT1();
        } else {
            CP_WAIT0();
        }
        __syncthreads();

        const uint32_t sA = sb + (uint32_t)(ch & 1) * STAGE;
        const uint32_t sX = sA + A_SIZE;
        const uint32_t aRow = (uint32_t)(e_w + (lane & 15)) * A_ROWB + (uint32_t)(lane >> 4) * 16;

#pragma unroll
        for (int kh = 0; kh < 2; ++kh) {
            const uint32_t kb = (uint32_t)kh * 32;
            // ---- B fragments: X and X-shift, hi/lo ----
            uint32_t bX[2][4][2], bS[2][4][2];
#pragma unroll
            for (int h = 0; h < 2; ++h) {
                uint32_t r1[4], r2[4];
                uint32_t rowa = sX + h * X_PLANE + (uint32_t)(i_w + lane) * A_ROWB + kb;
                ldsm_x4(r1, rowa);
                ldsm_x4(r2, rowa + 16);
#pragma unroll
                for (int nt = 0; nt < 4; nt++) { bX[h][nt][0] = r1[nt]; bX[h][nt][1] = r2[nt]; }
                uint32_t rowb = rowa + A_ROWB;   // rows +1 (shifted x)
                ldsm_x4(r1, rowb);
                ldsm_x4(r2, rowb + 16);
#pragma unroll
                for (int nt = 0; nt < 4; nt++) { bS[h][nt][0] = r1[nt]; bS[h][nt][1] = r2[nt]; }
            }
            // ---- weight sets: s=0 (odd, x[i]), 1 (even, x[i]), 2 (odd, x[i+1]) ----
#pragma unroll
            for (int s = 0; s < 3; ++s) {
                uint32_t aH[2][4], aL[2][4];
#pragma unroll
                for (int mt = 0; mt < 2; mt++) {
                    ldsm_x4(aH[mt], sA + (s * 2 + 0) * A_PLANE + aRow + mt * (16 * A_ROWB) + kb);
                    ldsm_x4(aL[mt], sA + (s * 2 + 1) * A_PLANE + aRow + mt * (16 * A_ROWB) + kb);
                }
#pragma unroll
                for (int mt = 0; mt < 2; mt++)
#pragma unroll
                    for (int nt = 0; nt < 4; nt++) {
                        float* d = (s == 1) ? accE[mt][nt] : accO[mt][nt];
                        const uint32_t* b0 = (s == 2) ? bS[0][nt] : bX[0][nt];
                        const uint32_t* b1 = (s == 2) ? bS[1][nt] : bX[1][nt];
                        mma_bf16(d, aH[mt], b0);   // hi * hi
                        mma_bf16(d, aH[mt], b1);   // hi * lo
                        mma_bf16(d, aL[mt], b0);   // lo * hi
                    }
            }
        }
        __syncthreads();
    }

    // ---- epilogue: interleave even/odd, add folded conv bias, write z ----
#pragma unroll
    for (int mt = 0; mt < 2; mt++) {
        int r0 = e0 + e_w + mt * 16 + (lane >> 2);
        float cb0 = g_cb[r0], cb1 = g_cb[r0 + 8];
#pragma unroll
        for (int nt = 0; nt < 4; nt++) {
            int ie = i0 + i_w + nt * 8 + (lane & 3) * 2;
            float4 v0, v1;
            v0.x = accE[mt][nt][0] + cb0; v0.y = accO[mt][nt][0] + cb0;
            v0.z = accE[mt][nt][1] + cb0; v0.w = accO[mt][nt][1] + cb0;
            v1.x = accE[mt][nt][2] + cb1; v1.y = accO[mt][nt][2] + cb1;
            v1.z = accE[mt][nt][3] + cb1; v1.w = accO[mt][nt][3] + cb1;
            *(float4*)(g_z + ((size_t)(b * D_ + r0)) * T_ + 2 * ie)       = v0;
            *(float4*)(g_z + ((size_t)(b * D_ + r0 + 8)) * T_ + 2 * ie)   = v1;
        }
    }
}

// ---------------- kernel 5: depthwise 17-tap AA + output bias ----------------
#define CHUNK 1024
__global__ __launch_bounds__(256) void aa_kernel(const float* __restrict__ aa,
                                                 const float* __restrict__ pb,
                                                 float* __restrict__ out) {
    __shared__ float s[CHUNK + 16];
    const int row = blockIdx.y;
    const int c0  = blockIdx.x * CHUNK;
    const int t   = threadIdx.x;
    const float* zr = g_z + (size_t)row * T_;

    for (int idx = t; idx < CHUNK + 16; idx += 256) {
        int g = c0 - 8 + idx;
        s[idx] = (g >= 0 && g < T_) ? zr[g] : 0.f;
    }
    float kc[KS];
#pragma unroll
    for (int j = 0; j < KS; j++) kc[j] = __ldg(&aa[j]);
    float bias = __ldg(&pb[row & (D_ - 1)]);
    __syncthreads();

    const int o = t * 4;
    float w[20];
#pragma unroll
    for (int q = 0; q < 5; q++) {
        float4 v = *(const float4*)&s[o + q * 4];
        w[q * 4 + 0] = v.x; w[q * 4 + 1] = v.y; w[q * 4 + 2] = v.z; w[q * 4 + 3] = v.w;
    }
    float acc0 = bias, acc1 = bias, acc2 = bias, acc3 = bias;
#pragma unroll
    for (int j = 0; j < KS; j++) {
        acc0 += kc[j] * w[j + 0];
        acc1 += kc[j] * w[j + 1];
        acc2 += kc[j] * w[j + 2];
        acc3 += kc[j] * w[j + 3];
    }
    float4 r; r.x = acc0; r.y = acc1; r.z = acc2; r.w = acc3;
    *(float4*)&out[(size_t)row * T_ + c0 + o] = r;
}

// ---------------- launch ----------------
extern "C" void kernel_launch(void* const* d_in, const int* in_sizes, int n_in,
                              void* d_out, int out_size) {
    const float* x      = (const float*)d_in[0];
    const float* conv_w = (const float*)d_in[1];
    const float* conv_b = (const float*)d_in[2];
    const float* aa_k   = (const float*)d_in[3];
    const float* proj_w = (const float*)d_in[4];
    const float* proj_b = (const float*)d_in[5];
    float* out = (float*)d_out;

    cudaFuncSetAttribute(gemm_kernel, cudaFuncAttributeMaxDynamicSharedMemorySize, GEMM_SMEM);

    fold_kernel<<<dim3(D_ / 32, D_ / 32), 256>>>(conv_w, proj_w);
    cb_kernel<<<dim3((D_ + 255) / 256), 256>>>(proj_w, conv_b);
    xprep_kernel<<<dim3(L_ / 32, D_ / 32, B_), 256>>>(x);
    zerox_kernel<<<dim3(B_ * D_ / 256), 256>>>();
    gemm_kernel<<<dim3(L_ / 64, D_ / 128, B_), 256, GEMM_SMEM>>>();
    aa_kernel<<<dim3(T_ / CHUNK, B_ * D_), 256>>>(aa_k, proj_b, out);
}

// round 4
// speedup vs baseline: 2.7868x; 2.0398x over previous
#include <cuda_runtime.h>
#include <cuda_fp16.h>
#include <cstdint>

#define B_   8
#define D_   512
#define L_   4096
#define LP_  4097
#define T_   8192
#define KS   17

// ---------------- device scratch ----------------
__device__ __half g_A[3][D_][D_];      // folded weights fp16 [k][e][c]
__device__ __half g_X[B_][LP_][D_];    // transposed x fp16 [b][i][c], row L zeroed
__device__ float  g_cb[D_];            // projected conv bias
__device__ __half g_z[(size_t)B_ * D_ * T_];   // intermediate (67 MB, fp16)

// ---------------- PTX helpers ----------------
__device__ __forceinline__ uint32_t smem_u32(const void* p) {
    uint32_t a;
    asm("{ .reg .u64 t; cvta.to.shared.u64 t, %1; cvt.u32.u64 %0, t; }" : "=r"(a) : "l"(p));
    return a;
}
__device__ __forceinline__ void cp16(uint32_t dst, const void* src) {
    asm volatile("cp.async.cg.shared.global [%0], [%1], 16;" :: "r"(dst), "l"(src));
}
#define CP_COMMIT()  asm volatile("cp.async.commit_group;" ::: "memory")
#define CP_WAIT1()   asm volatile("cp.async.wait_group 1;" ::: "memory")
#define CP_WAIT0()   asm volatile("cp.async.wait_group 0;" ::: "memory")

__device__ __forceinline__ void ldsm_x4(uint32_t* r, uint32_t addr) {
    asm volatile("ldmatrix.sync.aligned.m8n8.x4.shared.b16 {%0,%1,%2,%3}, [%4];"
                 : "=r"(r[0]), "=r"(r[1]), "=r"(r[2]), "=r"(r[3]) : "r"(addr));
}
__device__ __forceinline__ void mma_fp16(float* d, const uint32_t* a, const uint32_t* b) {
    asm volatile("mma.sync.aligned.m16n8k16.row.col.f32.f16.f16.f32 "
                 "{%0,%1,%2,%3}, {%4,%5,%6,%7}, {%8,%9}, {%0,%1,%2,%3};"
                 : "+f"(d[0]), "+f"(d[1]), "+f"(d[2]), "+f"(d[3])
                 : "r"(a[0]), "r"(a[1]), "r"(a[2]), "r"(a[3]), "r"(b[0]), "r"(b[1]));
}

// ---------------- kernel 1: fold weights -> fp16 ----------------
__global__ __launch_bounds__(256) void fold_kernel(const float* __restrict__ conv_w,
                                                   const float* __restrict__ proj_w) {
    __shared__ float sP[32][33];
    __shared__ float sW[3][32][33];
    const int c0 = blockIdx.x * 32;
    const int e0 = blockIdx.y * 32;
    const int t  = threadIdx.x;
    const int ld = t & 31, lr = t >> 5;
    const int el = t & 31, cb4 = (t >> 5) << 2;

    float acc[3][4];
#pragma unroll
    for (int k = 0; k < 3; k++)
#pragma unroll
        for (int j = 0; j < 4; j++) acc[k][j] = 0.f;

    for (int d0 = 0; d0 < D_; d0 += 32) {
#pragma unroll
        for (int p = 0; p < 4; p++) {
            int r = lr + p * 8;
            sP[r][ld] = proj_w[(size_t)(e0 + r) * D_ + d0 + ld];
#pragma unroll
            for (int k = 0; k < 3; k++)
                sW[k][r][ld] = conv_w[(size_t)(d0 + r) * (D_ * 3) + (size_t)(c0 + ld) * 3 + k];
        }
        __syncthreads();
#pragma unroll
        for (int dd = 0; dd < 32; dd++) {
            float pv = sP[el][dd];
#pragma unroll
            for (int j = 0; j < 4; j++)
#pragma unroll
                for (int k = 0; k < 3; k++)
                    acc[k][j] += sW[k][dd][cb4 + j] * pv;
        }
        __syncthreads();
    }
#pragma unroll
    for (int k = 0; k < 3; k++)
#pragma unroll
        for (int j = 0; j < 4; j++)
            g_A[k][e0 + el][c0 + cb4 + j] = __float2half_rn(acc[k][j]);
}

// ---------------- kernel 2: projected conv bias ----------------
__global__ __launch_bounds__(256) void cb_kernel(const float* __restrict__ proj_w,
                                                 const float* __restrict__ conv_b) {
    int e = blockIdx.x * 256 + threadIdx.x;
    if (e >= D_) return;
    float s = 0.f;
    const float* row = proj_w + (size_t)e * D_;
#pragma unroll 8
    for (int d = 0; d < D_; d++) s += row[d] * conv_b[d];
    g_cb[e] = s;
}

// ---------------- kernel 3: transpose x -> fp16 [b][i][c] ----------------
__global__ __launch_bounds__(256) void xprep_kernel(const float* __restrict__ x) {
    __shared__ float s[32][33];
    const int i0 = blockIdx.x * 32, c0 = blockIdx.y * 32, b = blockIdx.z;
    const int t = threadIdx.x, li = t & 31, lr = t >> 5;
#pragma unroll
    for (int p = 0; p < 4; p++) {
        int c = lr + p * 8;
        s[c][li] = x[((size_t)b * D_ + (c0 + c)) * L_ + i0 + li];
    }
    __syncthreads();
#pragma unroll
    for (int p = 0; p < 4; p++) {
        int i = lr + p * 8;
        g_X[b][i0 + i][c0 + li] = __float2half_rn(s[li][i]);
    }
}

__global__ __launch_bounds__(256) void zerox_kernel() {
    int idx = blockIdx.x * 256 + threadIdx.x;   // 8*512 = 4096
    int b = idx >> 9, c = idx & 511;
    g_X[b][L_][c] = __float2half_rn(0.f);
}

// ---------------- kernel 4: single-pass fp16 HMMA GEMM ----------------
// CTA tile: 128 e x 128 i, 512 threads (16 warps, 4e x 4i), warp tile 32x32.
// K chunks of 64, double-buffered cp.async. smem rows 144B (128 data + 16 pad).
#define KC      64
#define NCH     (D_ / KC)            // 8
#define ROWB    144
#define A_PLANE (128 * ROWB)         // 18432
#define A_SIZE  (3 * A_PLANE)        // 55296
#define X_ROWS  129
#define X_SIZE  (X_ROWS * ROWB)      // 18576
#define STAGE   (A_SIZE + X_SIZE)    // 73872
#define GEMM_SMEM (2 * STAGE)        // 147744

__device__ __forceinline__ void load_stage(uint32_t sb, int st, int ch,
                                           int e0, int i0, int b, int t) {
    const int c0 = ch * KC;
    const uint32_t base = sb + (uint32_t)st * STAGE;
    // A: 3 planes x 128 rows x 8 chunks of 16B = 3072 ops (6/thread @512)
#pragma unroll
    for (int p = 0; p < 6; p++) {
        int idx = p * 512 + t;
        int plane = idx >> 10;
        int rem = idx & 1023;
        int row = rem >> 3, cb = rem & 7;
        const __half* src = &g_A[plane][0][0] + (size_t)(e0 + row) * D_ + c0 + cb * 8;
        cp16(base + plane * A_PLANE + row * ROWB + cb * 16, src);
    }
    // X: 129 rows x 8 chunks = 1032 ops
    for (int idx = t; idx < X_ROWS * 8; idx += 512) {
        int row = idx >> 3, cb = idx & 7;
        const __half* src = &g_X[b][0][0] + (size_t)(i0 + row) * D_ + c0 + cb * 8;
        cp16(base + A_SIZE + row * ROWB + cb * 16, src);
    }
}

__global__ void __launch_bounds__(512, 1) gemm_kernel() {
    extern __shared__ char smem[];
    const uint32_t sb = smem_u32(smem);
    const int t = threadIdx.x, wid = t >> 5, lane = t & 31;
    const int i0 = blockIdx.x * 128, e0 = blockIdx.y * 128, b = blockIdx.z;
    const int e_w = (wid & 3) * 32;
    const int i_w = (wid >> 2) * 32;

    float accE[2][4][4], accO[2][4][4];
#pragma unroll
    for (int mt = 0; mt < 2; mt++)
#pragma unroll
        for (int nt = 0; nt < 4; nt++)
#pragma unroll
            for (int j = 0; j < 4; j++) { accE[mt][nt][j] = 0.f; accO[mt][nt][j] = 0.f; }

    load_stage(sb, 0, 0, e0, i0, b, t);
    CP_COMMIT();

    for (int ch = 0; ch < NCH; ++ch) {
        if (ch + 1 < NCH) {
            load_stage(sb, (ch + 1) & 1, ch + 1, e0, i0, b, t);
            CP_COMMIT();
            CP_WAIT1();
        } else {
            CP_WAIT0();
        }
        __syncthreads();

        const uint32_t sA = sb + (uint32_t)(ch & 1) * STAGE;
        const uint32_t sX = sA + A_SIZE;
        const uint32_t aRow = (uint32_t)(e_w + (lane & 15)) * ROWB + (uint32_t)(lane >> 4) * 16;
        const uint32_t xRow = sX + (uint32_t)(i_w + lane) * ROWB;

#pragma unroll
        for (int kh = 0; kh < 4; ++kh) {
            const uint32_t kb = (uint32_t)kh * 32;
            // B fragments: x[i] and x[i+1]
            uint32_t bX[4][2], bS[4][2];
            {
                uint32_t r1[4], r2[4];
                ldsm_x4(r1, xRow + kb);
                ldsm_x4(r2, xRow + kb + 16);
#pragma unroll
                for (int nt = 0; nt < 4; nt++) { bX[nt][0] = r1[nt]; bX[nt][1] = r2[nt]; }
                ldsm_x4(r1, xRow + ROWB + kb);
                ldsm_x4(r2, xRow + ROWB + kb + 16);
#pragma unroll
                for (int nt = 0; nt < 4; nt++) { bS[nt][0] = r1[nt]; bS[nt][1] = r2[nt]; }
            }
            // weight sets: s=0 (odd, x[i]), s=1 (even, x[i]), s=2 (odd, x[i+1])
#pragma unroll
            for (int s = 0; s < 3; ++s) {
                uint32_t aF[2][4];
#pragma unroll
                for (int mt = 0; mt < 2; mt++)
                    ldsm_x4(aF[mt], sA + s * A_PLANE + aRow + mt * (16 * ROWB) + kb);
#pragma unroll
                for (int mt = 0; mt < 2; mt++)
#pragma unroll
                    for (int nt = 0; nt < 4; nt++) {
                        float* d = (s == 1) ? accE[mt][nt] : accO[mt][nt];
                        mma_fp16(d, aF[mt], (s == 2) ? bS[nt] : bX[nt]);
                    }
            }
        }
        __syncthreads();
    }

    // ---- epilogue: interleave even/odd, add folded conv bias, write fp16 z ----
#pragma unroll
    for (int mt = 0; mt < 2; mt++) {
        int r0 = e0 + e_w + mt * 16 + (lane >> 2);
        float cb0 = g_cb[r0], cb1 = g_cb[r0 + 8];
#pragma unroll
        for (int nt = 0; nt < 4; nt++) {
            int ie = i0 + i_w + nt * 8 + (lane & 3) * 2;
            __half2 p0 = __floats2half2_rn(accE[mt][nt][0] + cb0, accO[mt][nt][0] + cb0);
            __half2 p1 = __floats2half2_rn(accE[mt][nt][1] + cb0, accO[mt][nt][1] + cb0);
            __half2 p2 = __floats2half2_rn(accE[mt][nt][2] + cb1, accO[mt][nt][2] + cb1);
            __half2 p3 = __floats2half2_rn(accE[mt][nt][3] + cb1, accO[mt][nt][3] + cb1);
            uint2 u0, u1;
            u0.x = *(uint32_t*)&p0; u0.y = *(uint32_t*)&p1;
            u1.x = *(uint32_t*)&p2; u1.y = *(uint32_t*)&p3;
            *(uint2*)(g_z + ((size_t)(b * D_ + r0)) * T_ + 2 * ie)     = u0;
            *(uint2*)(g_z + ((size_t)(b * D_ + r0 + 8)) * T_ + 2 * ie) = u1;
        }
    }
}

// ---------------- kernel 5: depthwise 17-tap AA + output bias ----------------
#define CHUNK 2048
__global__ __launch_bounds__(256) void aa_kernel(const float* __restrict__ aa,
                                                 const float* __restrict__ pb,
                                                 float* __restrict__ out) {
    __shared__ float s[CHUNK + 16];
    const int row = blockIdx.y;
    const int c0  = blockIdx.x * CHUNK;
    const int t   = threadIdx.x;
    const __half* zr = g_z + (size_t)row * T_;

    for (int idx = t; idx < CHUNK + 16; idx += 256) {
        int g = c0 - 8 + idx;
        s[idx] = (g >= 0 && g < T_) ? __half2float(zr[g]) : 0.f;
    }
    float kc[KS];
#pragma unroll
    for (int j = 0; j < KS; j++) kc[j] = __ldg(&aa[j]);
    float bias = __ldg(&pb[row & (D_ - 1)]);
    __syncthreads();

    const int o = t * 8;
    float w[24];
#pragma unroll
    for (int q = 0; q < 6; q++) {
        float4 v = *(const float4*)&s[o + q * 4];
        w[q * 4 + 0] = v.x; w[q * 4 + 1] = v.y; w[q * 4 + 2] = v.z; w[q * 4 + 3] = v.w;
    }
    float acc[8];
#pragma unroll
    for (int r = 0; r < 8; r++) acc[r] = bias;
#pragma unroll
    for (int j = 0; j < KS; j++)
#pragma unroll
        for (int r = 0; r < 8; r++)
            acc[r] += kc[j] * w[j + r];
    float4 v0, v1;
    v0.x = acc[0]; v0.y = acc[1]; v0.z = acc[2]; v0.w = acc[3];
    v1.x = acc[4]; v1.y = acc[5]; v1.z = acc[6]; v1.w = acc[7];
    float* op = out + (size_t)row * T_ + c0 + o;
    *(float4*)op = v0;
    *(float4*)(op + 4) = v1;
}

// ---------------- launch ----------------
extern "C" void kernel_launch(void* const* d_in, const int* in_sizes, int n_in,
                              void* d_out, int out_size) {
    const float* x      = (const float*)d_in[0];
    const float* conv_w = (const float*)d_in[1];
    const float* conv_b = (const float*)d_in[2];
    const float* aa_k   = (const float*)d_in[3];
    const float* proj_w = (const float*)d_in[4];
    const float* proj_b = (const float*)d_in[5];
    float* out = (float*)d_out;

    cudaFuncSetAttribute(gemm_kernel, cudaFuncAttributeMaxDynamicSharedMemorySize, GEMM_SMEM);

    fold_kernel<<<dim3(D_ / 32, D_ / 32), 256>>>(conv_w, proj_w);
    cb_kernel<<<dim3((D_ + 255) / 256), 256>>>(proj_w, conv_b);
    xprep_kernel<<<dim3(L_ / 32, D_ / 32, B_), 256>>>(x);
    zerox_kernel<<<dim3(B_ * D_ / 256), 256>>>();
    gemm_kernel<<<dim3(L_ / 128, D_ / 128, B_), 512, GEMM_SMEM>>>();
    aa_kernel<<<dim3(T_ / CHUNK, B_ * D_), 256>>>(aa_k, proj_b, out);
}

// round 5
// speedup vs baseline: 2.8743x; 1.0314x over previous
#include <cuda_runtime.h>
#include <cuda_fp16.h>
#include <cstdint>

#define B_   8
#define D_   512
#define L_   4096
#define LP_  4097
#define T_   8192
#define KS   17

// ---------------- device scratch ----------------
__device__ __half g_A[3][D_][D_];      // folded weights fp16 [k][e][c]
__device__ __half g_X[B_][LP_][D_];    // transposed x fp16 [b][i][c], row L zeroed
__device__ float  g_cb[D_];            // projected conv bias
__device__ __half g_z[(size_t)B_ * D_ * T_];   // intermediate (67 MB, fp16)

// ---------------- PTX helpers ----------------
__device__ __forceinline__ uint32_t smem_u32(const void* p) {
    uint32_t a;
    asm("{ .reg .u64 t; cvta.to.shared.u64 t, %1; cvt.u32.u64 %0, t; }" : "=r"(a) : "l"(p));
    return a;
}
__device__ __forceinline__ void cp16(uint32_t dst, const void* src) {
    asm volatile("cp.async.cg.shared.global [%0], [%1], 16;" :: "r"(dst), "l"(src));
}
#define CP_COMMIT()  asm volatile("cp.async.commit_group;" ::: "memory")
#define CP_WAIT2()   asm volatile("cp.async.wait_group 2;" ::: "memory")

__device__ __forceinline__ void ldsm_x4(uint32_t* r, uint32_t addr) {
    asm volatile("ldmatrix.sync.aligned.m8n8.x4.shared.b16 {%0,%1,%2,%3}, [%4];"
                 : "=r"(r[0]), "=r"(r[1]), "=r"(r[2]), "=r"(r[3]) : "r"(addr));
}
__device__ __forceinline__ void mma_fp16(float* d, const uint32_t* a, const uint32_t* b) {
    asm volatile("mma.sync.aligned.m16n8k16.row.col.f32.f16.f16.f32 "
                 "{%0,%1,%2,%3}, {%4,%5,%6,%7}, {%8,%9}, {%0,%1,%2,%3};"
                 : "+f"(d[0]), "+f"(d[1]), "+f"(d[2]), "+f"(d[3])
                 : "r"(a[0]), "r"(a[1]), "r"(a[2]), "r"(a[3]), "r"(b[0]), "r"(b[1]));
}
__device__ __forceinline__ unsigned long long pack2(float lo, float hi) {
    unsigned long long r;
    asm("mov.b64 %0, {%1, %2};" : "=l"(r) : "f"(lo), "f"(hi));
    return r;
}
__device__ __forceinline__ unsigned long long fma2(unsigned long long a,
                                                   unsigned long long b,
                                                   unsigned long long c) {
    unsigned long long d;
    asm("fma.rn.f32x2 %0, %1, %2, %3;" : "=l"(d) : "l"(a), "l"(b), "l"(c));
    return d;
}
__device__ __forceinline__ float2 unpack2(unsigned long long v) {
    float2 f;
    asm("mov.b64 {%0, %1}, %2;" : "=f"(f.x), "=f"(f.y) : "l"(v));
    return f;
}

// ---------------- kernel 1: fold weights -> fp16 (register-blocked) ----------
// block tile: 64 e x 32 c (x3 k).  thread: 4 e x 2 c x 3 k.
__global__ __launch_bounds__(256) void fold_kernel(const float* __restrict__ conv_w,
                                                   const float* __restrict__ proj_w) {
    __shared__ float sP[32][68];     // [d][e]
    __shared__ float sW[32][98];     // [d][c*3+k]
    const int c0 = blockIdx.x * 32;
    const int e0 = blockIdx.y * 64;
    const int t  = threadIdx.x;
    const int tx = t & 15;           // c group (2 c)
    const int ty = t >> 4;           // e group (4 e)

    float acc[3][4][2];
#pragma unroll
    for (int k = 0; k < 3; k++)
#pragma unroll
        for (int e = 0; e < 4; e++) { acc[k][e][0] = 0.f; acc[k][e][1] = 0.f; }

    for (int d0 = 0; d0 < D_; d0 += 32) {
        // P: 64 e x 32 d  (2048 floats, 8/thread)
#pragma unroll
        for (int p = 0; p < 8; p++) {
            int idx = p * 256 + t;
            int e = idx >> 5, d = idx & 31;
            sP[d][e] = proj_w[(size_t)(e0 + e) * D_ + d0 + d];
        }
        // W: 32 d x (32 c * 3 k)  (3072 floats, 12/thread)
#pragma unroll
        for (int p = 0; p < 12; p++) {
            int idx = p * 256 + t;
            int d = idx / 96, rem = idx % 96;
            sW[d][rem] = conv_w[(size_t)(d0 + d) * (D_ * 3) + (size_t)c0 * 3 + rem];
        }
        __syncthreads();
#pragma unroll
        for (int dd = 0; dd < 32; dd++) {
            float pe[4];
#pragma unroll
            for (int e = 0; e < 4; e++) pe[e] = sP[dd][ty * 4 + e];
#pragma unroll
            for (int c = 0; c < 2; c++)
#pragma unroll
                for (int k = 0; k < 3; k++) {
                    float w = sW[dd][(tx * 2 + c) * 3 + k];
#pragma unroll
                    for (int e = 0; e < 4; e++) acc[k][e][c] += pe[e] * w;
                }
        }
        __syncthreads();
    }
#pragma unroll
    for (int k = 0; k < 3; k++)
#pragma unroll
        for (int e = 0; e < 4; e++)
#pragma unroll
            for (int c = 0; c < 2; c++)
                g_A[k][e0 + ty * 4 + e][c0 + tx * 2 + c] = __float2half_rn(acc[k][e][c]);
}

// ---------------- kernel 2: projected conv bias ----------------
__global__ __launch_bounds__(256) void cb_kernel(const float* __restrict__ proj_w,
                                                 const float* __restrict__ conv_b) {
    int e = blockIdx.x * 256 + threadIdx.x;
    if (e >= D_) return;
    float s = 0.f;
    const float* row = proj_w + (size_t)e * D_;
#pragma unroll 8
    for (int d = 0; d < D_; d++) s += row[d] * conv_b[d];
    g_cb[e] = s;
}

// ---------------- kernel 3: transpose x -> fp16 [b][i][c] (+ zero row L) ----
__global__ __launch_bounds__(256) void xprep_kernel(const float* __restrict__ x) {
    __shared__ float s[32][33];
    const int i0 = blockIdx.x * 32, c0 = blockIdx.y * 32, b = blockIdx.z;
    const int t = threadIdx.x, li = t & 31, lr = t >> 5;
#pragma unroll
    for (int p = 0; p < 4; p++) {
        int c = lr + p * 8;
        s[c][li] = x[((size_t)b * D_ + (c0 + c)) * L_ + i0 + li];
    }
    if (blockIdx.x == 0 && t < 32)
        g_X[b][L_][c0 + t] = __float2half_rn(0.f);
    __syncthreads();
#pragma unroll
    for (int p = 0; p < 4; p++) {
        int i = lr + p * 8;
        g_X[b][i0 + i][c0 + li] = __float2half_rn(s[li][i]);
    }
}

// ---------------- kernel 4: single-pass fp16 HMMA GEMM, 3-stage pipeline ----
#define KC      64
#define NCH     (D_ / KC)            // 8
#define ROWB    144
#define A_PLANE (128 * ROWB)         // 18432
#define A_SIZE  (3 * A_PLANE)        // 55296
#define X_ROWS  129
#define X_SIZE  (X_ROWS * ROWB)      // 18576
#define STAGE   (A_SIZE + X_SIZE)    // 73872
#define NSTAGE  3
#define GEMM_SMEM (NSTAGE * STAGE)   // 221616

__device__ __forceinline__ void load_stage(uint32_t sb, int st, int ch,
                                           int e0, int i0, int b, int t) {
    const int c0 = ch * KC;
    const uint32_t base = sb + (uint32_t)st * STAGE;
#pragma unroll
    for (int p = 0; p < 6; p++) {
        int idx = p * 512 + t;
        int plane = idx >> 10;
        int rem = idx & 1023;
        int row = rem >> 3, cb = rem & 7;
        const __half* src = &g_A[plane][0][0] + (size_t)(e0 + row) * D_ + c0 + cb * 8;
        cp16(base + plane * A_PLANE + row * ROWB + cb * 16, src);
    }
    for (int idx = t; idx < X_ROWS * 8; idx += 512) {
        int row = idx >> 3, cb = idx & 7;
        const __half* src = &g_X[b][0][0] + (size_t)(i0 + row) * D_ + c0 + cb * 8;
        cp16(base + A_SIZE + row * ROWB + cb * 16, src);
    }
}

__global__ void __launch_bounds__(512, 1) gemm_kernel() {
    extern __shared__ char smem[];
    const uint32_t sb = smem_u32(smem);
    const int t = threadIdx.x, wid = t >> 5, lane = t & 31;
    const int i0 = blockIdx.x * 128, e0 = blockIdx.y * 128, b = blockIdx.z;
    const int e_w = (wid & 3) * 32;
    const int i_w = (wid >> 2) * 32;

    float accE[2][4][4], accO[2][4][4];
#pragma unroll
    for (int mt = 0; mt < 2; mt++)
#pragma unroll
        for (int nt = 0; nt < 4; nt++)
#pragma unroll
            for (int j = 0; j < 4; j++) { accE[mt][nt][j] = 0.f; accO[mt][nt][j] = 0.f; }

    load_stage(sb, 0, 0, e0, i0, b, t);
    CP_COMMIT();
    load_stage(sb, 1, 1, e0, i0, b, t);
    CP_COMMIT();

    for (int ch = 0; ch < NCH; ++ch) {
        if (ch + 2 < NCH)
            load_stage(sb, (ch + 2) % NSTAGE, ch + 2, e0, i0, b, t);
        CP_COMMIT();
        CP_WAIT2();
        __syncthreads();

        const uint32_t sA = sb + (uint32_t)(ch % NSTAGE) * STAGE;
        const uint32_t sX = sA + A_SIZE;
        const uint32_t aRow = (uint32_t)(e_w + (lane & 15)) * ROWB + (uint32_t)(lane >> 4) * 16;
        const uint32_t xRow = sX + (uint32_t)(i_w + lane) * ROWB;

#pragma unroll
        for (int kh = 0; kh < 4; ++kh) {
            const uint32_t kb = (uint32_t)kh * 32;
            uint32_t bX[4][2], bS[4][2];
            {
                uint32_t r1[4], r2[4];
                ldsm_x4(r1, xRow + kb);
                ldsm_x4(r2, xRow + kb + 16);
#pragma unroll
                for (int nt = 0; nt < 4; nt++) { bX[nt][0] = r1[nt]; bX[nt][1] = r2[nt]; }
                ldsm_x4(r1, xRow + ROWB + kb);
                ldsm_x4(r2, xRow + ROWB + kb + 16);
#pragma unroll
                for (int nt = 0; nt < 4; nt++) { bS[nt][0] = r1[nt]; bS[nt][1] = r2[nt]; }
            }
#pragma unroll
            for (int s = 0; s < 3; ++s) {
                uint32_t aF[2][4];
#pragma unroll
                for (int mt = 0; mt < 2; mt++)
                    ldsm_x4(aF[mt], sA + s * A_PLANE + aRow + mt * (16 * ROWB) + kb);
#pragma unroll
                for (int mt = 0; mt < 2; mt++)
#pragma unroll
                    for (int nt = 0; nt < 4; nt++) {
                        float* d = (s == 1) ? accE[mt][nt] : accO[mt][nt];
                        mma_fp16(d, aF[mt], (s == 2) ? bS[nt] : bX[nt]);
                    }
            }
        }
        __syncthreads();
    }

    // ---- epilogue: interleave even/odd, add folded conv bias, write fp16 z ----
#pragma unroll
    for (int mt = 0; mt < 2; mt++) {
        int r0 = e0 + e_w + mt * 16 + (lane >> 2);
        float cb0 = g_cb[r0], cb1 = g_cb[r0 + 8];
#pragma unroll
        for (int nt = 0; nt < 4; nt++) {
            int ie = i0 + i_w + nt * 8 + (lane & 3) * 2;
            __half2 p0 = __floats2half2_rn(accE[mt][nt][0] + cb0, accO[mt][nt][0] + cb0);
            __half2 p1 = __floats2half2_rn(accE[mt][nt][1] + cb0, accO[mt][nt][1] + cb0);
            __half2 p2 = __floats2half2_rn(accE[mt][nt][2] + cb1, accO[mt][nt][2] + cb1);
            __half2 p3 = __floats2half2_rn(accE[mt][nt][3] + cb1, accO[mt][nt][3] + cb1);
            uint2 u0, u1;
            u0.x = *(uint32_t*)&p0; u0.y = *(uint32_t*)&p1;
            u1.x = *(uint32_t*)&p2; u1.y = *(uint32_t*)&p3;
            *(uint2*)(g_z + ((size_t)(b * D_ + r0)) * T_ + 2 * ie)     = u0;
            *(uint2*)(g_z + ((size_t)(b * D_ + r0 + 8)) * T_ + 2 * ie) = u1;
        }
    }
}

// ---------------- kernel 5: depthwise 17-tap AA (f32x2) + output bias -------
#define HALF_T 4096
__global__ __launch_bounds__(128, 2) void aa_kernel(const float* __restrict__ aa,
                                                    const float* __restrict__ pb,
                                                    float* __restrict__ out) {
    __shared__ float s[HALF_T + 16];
    const int row  = blockIdx.x >> 1;
    const int half = blockIdx.x & 1;
    const int c0   = half * HALF_T;
    const int t    = threadIdx.x;
    const __half* zr = g_z + (size_t)row * T_;

    // interior: 4096 halfs = 512 uint4, 4 per thread
#pragma unroll
    for (int p = 0; p < 4; p++) {
        int idx = p * 128 + t;
        uint4 v = *(const uint4*)(zr + c0 + idx * 8);
        const __half2* h = (const __half2*)&v;
        float2 f0 = __half22float2(h[0]);
        float2 f1 = __half22float2(h[1]);
        float2 f2 = __half22float2(h[2]);
        float2 f3 = __half22float2(h[3]);
        float4 a; a.x = f0.x; a.y = f0.y; a.z = f1.x; a.w = f1.y;
        float4 c; c.x = f2.x; c.y = f2.y; c.z = f3.x; c.w = f3.y;
        *(float4*)&s[8 + idx * 8]     = a;
        *(float4*)&s[8 + idx * 8 + 4] = c;
    }
    if (t < 8) {
        int g = c0 - 8 + t;
        s[t] = (g >= 0) ? __half2float(zr[g]) : 0.f;
    } else if (t < 16) {
        int g = c0 + HALF_T + (t - 8);
        s[HALF_T + 8 + (t - 8)] = (g < T_) ? __half2float(zr[g]) : 0.f;
    }
    float kc[KS];
#pragma unroll
    for (int j = 0; j < KS; j++) kc[j] = __ldg(&aa[j]);
    float bias = __ldg(&pb[row & (D_ - 1)]);
    __syncthreads();

    const int o0 = t * 32;
    float w[48];
#pragma unroll
    for (int q = 0; q < 12; q++)
        *(float4*)&w[q * 4] = *(const float4*)&s[o0 + q * 4];

    unsigned long long E[24], O[23], acc[16];
#pragma unroll
    for (int m = 0; m < 24; m++) E[m] = pack2(w[2 * m], w[2 * m + 1]);
#pragma unroll
    for (int m = 0; m < 23; m++) O[m] = pack2(w[2 * m + 1], w[2 * m + 2]);
    unsigned long long b2 = pack2(bias, bias);
#pragma unroll
    for (int p = 0; p < 16; p++) acc[p] = b2;

#pragma unroll
    for (int j = 0; j < KS; j++) {
        unsigned long long k2 = pack2(kc[j], kc[j]);
        const unsigned long long* src = (j & 1) ? &O[j >> 1] : &E[j >> 1];
#pragma unroll
        for (int p = 0; p < 16; p++) acc[p] = fma2(k2, src[p], acc[p]);
    }

    float* op = out + (size_t)row * T_ + c0 + o0;
#pragma unroll
    for (int p = 0; p < 8; p++) {
        float2 a = unpack2(acc[2 * p]);
        float2 bq = unpack2(acc[2 * p + 1]);
        float4 v; v.x = a.x; v.y = a.y; v.z = bq.x; v.w = bq.y;
        *(float4*)&op[p * 4] = v;
    }
}

// ---------------- launch ----------------
extern "C" void kernel_launch(void* const* d_in, const int* in_sizes, int n_in,
                              void* d_out, int out_size) {
    const float* x      = (const float*)d_in[0];
    const float* conv_w = (const float*)d_in[1];
    const float* conv_b = (const float*)d_in[2];
    const float* aa_k   = (const float*)d_in[3];
    const float* proj_w = (const float*)d_in[4];
    const float* proj_b = (const float*)d_in[5];
    float* out = (float*)d_out;

    cudaFuncSetAttribute(gemm_kernel, cudaFuncAttributeMaxDynamicSharedMemorySize, GEMM_SMEM);

    fold_kernel<<<dim3(D_ / 32, D_ / 64), 256>>>(conv_w, proj_w);
    cb_kernel<<<dim3((D_ + 255) / 256), 256>>>(proj_w, conv_b);
    xprep_kernel<<<dim3(L_ / 32, D_ / 32, B_), 256>>>(x);
    gemm_kernel<<<dim3(L_ / 128, D_ / 128, B_), 512, GEMM_SMEM>>>();
    aa_kernel<<<dim3(B_ * D_ * 2), 128>>>(aa_k, proj_b, out);
}

// round 6
// speedup vs baseline: 3.2438x; 1.1286x over previous
#include <cuda_runtime.h>
#include <cuda_fp16.h>
#include <cstdint>

#define B_   8
#define D_   512
#define L_   4096
#define LP_  4097
#define T_   8192
#define KS   17

// ---------------- device scratch ----------------
__device__ __half g_A[3][D_][D_];      // folded weights fp16 [k][e][c]
__device__ __half g_X[B_][LP_][D_];    // transposed x fp16 [b][i][c], row L zeroed
__device__ float  g_cb[D_];            // projected conv bias
__device__ __half g_z[(size_t)B_ * D_ * T_];   // intermediate (67 MB, fp16)

// ---------------- PTX helpers ----------------
__device__ __forceinline__ uint32_t smem_u32(const void* p) {
    uint32_t a;
    asm("{ .reg .u64 t; cvta.to.shared.u64 t, %1; cvt.u32.u64 %0, t; }" : "=r"(a) : "l"(p));
    return a;
}
__device__ __forceinline__ void cp16(uint32_t dst, const void* src) {
    asm volatile("cp.async.cg.shared.global [%0], [%1], 16;" :: "r"(dst), "l"(src));
}
#define CP_COMMIT()  asm volatile("cp.async.commit_group;" ::: "memory")
#define CP_WAIT2()   asm volatile("cp.async.wait_group 2;" ::: "memory")

__device__ __forceinline__ void ldsm_x4(uint32_t* r, uint32_t addr) {
    asm volatile("ldmatrix.sync.aligned.m8n8.x4.shared.b16 {%0,%1,%2,%3}, [%4];"
                 : "=r"(r[0]), "=r"(r[1]), "=r"(r[2]), "=r"(r[3]) : "r"(addr));
}
__device__ __forceinline__ void mma_fp16(float* d, const uint32_t* a, const uint32_t* b) {
    asm volatile("mma.sync.aligned.m16n8k16.row.col.f32.f16.f16.f32 "
                 "{%0,%1,%2,%3}, {%4,%5,%6,%7}, {%8,%9}, {%0,%1,%2,%3};"
                 : "+f"(d[0]), "+f"(d[1]), "+f"(d[2]), "+f"(d[3])
                 : "r"(a[0]), "r"(a[1]), "r"(a[2]), "r"(a[3]), "r"(b[0]), "r"(b[1]));
}
__device__ __forceinline__ unsigned long long pack2(float lo, float hi) {
    unsigned long long r;
    asm("mov.b64 %0, {%1, %2};" : "=l"(r) : "f"(lo), "f"(hi));
    return r;
}
__device__ __forceinline__ unsigned long long fma2(unsigned long long a,
                                                   unsigned long long b,
                                                   unsigned long long c) {
    unsigned long long d;
    asm("fma.rn.f32x2 %0, %1, %2, %3;" : "=l"(d) : "l"(a), "l"(b), "l"(c));
    return d;
}
__device__ __forceinline__ float2 unpack2(unsigned long long v) {
    float2 f;
    asm("mov.b64 {%0, %1}, %2;" : "=f"(f.x), "=f"(f.y) : "l"(v));
    return f;
}

// ---------------- kernel 1 (merged prep): xprep | fold | cb -----------------
// blocks [0, 16384)          : xprep  (transpose x -> fp16 [b][i][c])
// blocks [16384, 16512)      : fold   (G = proj_w . conv_w -> fp16 [k][e][c])
// blocks [16512, 16514)      : cb     (projected conv bias)
#define XPREP_BLKS 16384
#define FOLD_BLKS  128
__global__ __launch_bounds__(256) void prep_kernel(const float* __restrict__ x,
                                                   const float* __restrict__ conv_w,
                                                   const float* __restrict__ conv_b,
                                                   const float* __restrict__ proj_w) {
    __shared__ float sm[32 * 68 + 32 * 98];    // fold's demand (21.2 KB), reused by xprep
    const int bx = blockIdx.x;
    const int t  = threadIdx.x;

    if (bx < XPREP_BLKS) {
        // ---- xprep ----
        float (*s)[33] = (float (*)[33])sm;
        const int i0 = (bx & 127) * 32;
        const int c0 = ((bx >> 7) & 15) * 32;
        const int b  = bx >> 11;
        const int li = t & 31, lr = t >> 5;
#pragma unroll
        for (int p = 0; p < 4; p++) {
            int c = lr + p * 8;
            s[c][li] = x[((size_t)b * D_ + (c0 + c)) * L_ + i0 + li];
        }
        if (i0 == 0 && t < 32)
            g_X[b][L_][c0 + t] = __float2half_rn(0.f);
        __syncthreads();
#pragma unroll
        for (int p = 0; p < 4; p++) {
            int i = lr + p * 8;
            g_X[b][i0 + i][c0 + li] = __float2half_rn(s[li][i]);
        }
    } else if (bx < XPREP_BLKS + FOLD_BLKS) {
        // ---- fold: block tile 64 e x 32 c x 3 k; thread 4e x 2c x 3k ----
        float (*sP)[68] = (float (*)[68])sm;             // [d][e]
        float (*sW)[98] = (float (*)[98])(sm + 32 * 68); // [d][c*3+k]
        const int f  = bx - XPREP_BLKS;
        const int c0 = (f & 15) * 32;
        const int e0 = (f >> 4) * 64;
        const int tx = t & 15;
        const int ty = t >> 4;

        float acc[3][4][2];
#pragma unroll
        for (int k = 0; k < 3; k++)
#pragma unroll
            for (int e = 0; e < 4; e++) { acc[k][e][0] = 0.f; acc[k][e][1] = 0.f; }

        for (int d0 = 0; d0 < D_; d0 += 32) {
#pragma unroll
            for (int p = 0; p < 8; p++) {
                int idx = p * 256 + t;
                int e = idx >> 5, d = idx & 31;
                sP[d][e] = proj_w[(size_t)(e0 + e) * D_ + d0 + d];
            }
#pragma unroll
            for (int p = 0; p < 12; p++) {
                int idx = p * 256 + t;
                int d = idx / 96, rem = idx % 96;
                sW[d][rem] = conv_w[(size_t)(d0 + d) * (D_ * 3) + (size_t)c0 * 3 + rem];
            }
            __syncthreads();
#pragma unroll
            for (int dd = 0; dd < 32; dd++) {
                float pe[4];
#pragma unroll
                for (int e = 0; e < 4; e++) pe[e] = sP[dd][ty * 4 + e];
#pragma unroll
                for (int c = 0; c < 2; c++)
#pragma unroll
                    for (int k = 0; k < 3; k++) {
                        float w = sW[dd][(tx * 2 + c) * 3 + k];
#pragma unroll
                        for (int e = 0; e < 4; e++) acc[k][e][c] += pe[e] * w;
                    }
            }
            __syncthreads();
        }
#pragma unroll
        for (int k = 0; k < 3; k++)
#pragma unroll
            for (int e = 0; e < 4; e++)
#pragma unroll
                for (int c = 0; c < 2; c++)
                    g_A[k][e0 + ty * 4 + e][c0 + tx * 2 + c] = __float2half_rn(acc[k][e][c]);
    } else {
        // ---- cb ----
        int e = (bx - XPREP_BLKS - FOLD_BLKS) * 256 + t;
        if (e < D_) {
            float s = 0.f;
            const float* row = proj_w + (size_t)e * D_;
#pragma unroll 8
            for (int d = 0; d < D_; d++) s += row[d] * conv_b[d];
            g_cb[e] = s;
        }
    }
}

// ---------------- kernel 2: single-pass fp16 HMMA GEMM, 3-stage pipeline ----
#define KC      64
#define NCH     (D_ / KC)            // 8
#define ROWB    144
#define A_PLANE (128 * ROWB)         // 18432
#define A_SIZE  (3 * A_PLANE)        // 55296
#define X_ROWS  129
#define X_SIZE  (X_ROWS * ROWB)      // 18576
#define STAGE   (A_SIZE + X_SIZE)    // 73872
#define NSTAGE  3
#define GEMM_SMEM (NSTAGE * STAGE)   // 221616

__device__ __forceinline__ void load_stage(uint32_t sb, int st, int ch,
                                           int e0, int i0, int b, int t) {
    const int c0 = ch * KC;
    const uint32_t base = sb + (uint32_t)st * STAGE;
#pragma unroll
    for (int p = 0; p < 6; p++) {
        int idx = p * 512 + t;
        int plane = idx >> 10;
        int rem = idx & 1023;
        int row = rem >> 3, cb = rem & 7;
        const __half* src = &g_A[plane][0][0] + (size_t)(e0 + row) * D_ + c0 + cb * 8;
        cp16(base + plane * A_PLANE + row * ROWB + cb * 16, src);
    }
    for (int idx = t; idx < X_ROWS * 8; idx += 512) {
        int row = idx >> 3, cb = idx & 7;
        const __half* src = &g_X[b][0][0] + (size_t)(i0 + row) * D_ + c0 + cb * 8;
        cp16(base + A_SIZE + row * ROWB + cb * 16, src);
    }
}

__global__ void __launch_bounds__(512, 1) gemm_kernel() {
    extern __shared__ char smem[];
    const uint32_t sb = smem_u32(smem);
    const int t = threadIdx.x, wid = t >> 5, lane = t & 31;
    const int i0 = blockIdx.x * 128, e0 = blockIdx.y * 128, b = blockIdx.z;
    const int e_w = (wid & 3) * 32;
    const int i_w = (wid >> 2) * 32;

    float accE[2][4][4], accO[2][4][4];
#pragma unroll
    for (int mt = 0; mt < 2; mt++)
#pragma unroll
        for (int nt = 0; nt < 4; nt++)
#pragma unroll
            for (int j = 0; j < 4; j++) { accE[mt][nt][j] = 0.f; accO[mt][nt][j] = 0.f; }

    load_stage(sb, 0, 0, e0, i0, b, t);
    CP_COMMIT();
    load_stage(sb, 1, 1, e0, i0, b, t);
    CP_COMMIT();

    for (int ch = 0; ch < NCH; ++ch) {
        if (ch + 2 < NCH)
            load_stage(sb, (ch + 2) % NSTAGE, ch + 2, e0, i0, b, t);
        CP_COMMIT();
        CP_WAIT2();
        __syncthreads();

        const uint32_t sA = sb + (uint32_t)(ch % NSTAGE) * STAGE;
        const uint32_t sX = sA + A_SIZE;
        const uint32_t aRow = (uint32_t)(e_w + (lane & 15)) * ROWB + (uint32_t)(lane >> 4) * 16;
        const uint32_t xRow = sX + (uint32_t)(i_w + lane) * ROWB;

#pragma unroll
        for (int kh = 0; kh < 4; ++kh) {
            const uint32_t kb = (uint32_t)kh * 32;
            uint32_t bX[4][2], bS[4][2];
            {
                uint32_t r1[4], r2[4];
                ldsm_x4(r1, xRow + kb);
                ldsm_x4(r2, xRow + kb + 16);
#pragma unroll
                for (int nt = 0; nt < 4; nt++) { bX[nt][0] = r1[nt]; bX[nt][1] = r2[nt]; }
                ldsm_x4(r1, xRow + ROWB + kb);
                ldsm_x4(r2, xRow + ROWB + kb + 16);
#pragma unroll
                for (int nt = 0; nt < 4; nt++) { bS[nt][0] = r1[nt]; bS[nt][1] = r2[nt]; }
            }
#pragma unroll
            for (int s = 0; s < 3; ++s) {
                uint32_t aF[2][4];
#pragma unroll
                for (int mt = 0; mt < 2; mt++)
                    ldsm_x4(aF[mt], sA + s * A_PLANE + aRow + mt * (16 * ROWB) + kb);
#pragma unroll
                for (int mt = 0; mt < 2; mt++)
#pragma unroll
                    for (int nt = 0; nt < 4; nt++) {
                        float* d = (s == 1) ? accE[mt][nt] : accO[mt][nt];
                        mma_fp16(d, aF[mt], (s == 2) ? bS[nt] : bX[nt]);
                    }
            }
        }
        __syncthreads();
    }

    // ---- epilogue: interleave even/odd, add folded conv bias, write fp16 z ----
#pragma unroll
    for (int mt = 0; mt < 2; mt++) {
        int r0 = e0 + e_w + mt * 16 + (lane >> 2);
        float cb0 = g_cb[r0], cb1 = g_cb[r0 + 8];
#pragma unroll
        for (int nt = 0; nt < 4; nt++) {
            int ie = i0 + i_w + nt * 8 + (lane & 3) * 2;
            __half2 p0 = __floats2half2_rn(accE[mt][nt][0] + cb0, accO[mt][nt][0] + cb0);
            __half2 p1 = __floats2half2_rn(accE[mt][nt][1] + cb0, accO[mt][nt][1] + cb0);
            __half2 p2 = __floats2half2_rn(accE[mt][nt][2] + cb1, accO[mt][nt][2] + cb1);
            __half2 p3 = __floats2half2_rn(accE[mt][nt][3] + cb1, accO[mt][nt][3] + cb1);
            uint2 u0, u1;
            u0.x = *(uint32_t*)&p0; u0.y = *(uint32_t*)&p1;
            u1.x = *(uint32_t*)&p2; u1.y = *(uint32_t*)&p3;
            *(uint2*)(g_z + ((size_t)(b * D_ + r0)) * T_ + 2 * ie)     = u0;
            *(uint2*)(g_z + ((size_t)(b * D_ + r0 + 8)) * T_ + 2 * ie) = u1;
        }
    }
}

// ---------------- kernel 3: depthwise 17-tap AA, direct-gmem, f32x2 ---------
// 8 outputs/thread, 24-half window via 3x LDG.128 (L1 absorbs neighbor overlap)
__device__ __forceinline__ void unp8(uint4 v, float* w) {
    const __half2* h = (const __half2*)&v;
    float2 f0 = __half22float2(h[0]);
    float2 f1 = __half22float2(h[1]);
    float2 f2 = __half22float2(h[2]);
    float2 f3 = __half22float2(h[3]);
    w[0] = f0.x; w[1] = f0.y; w[2] = f1.x; w[3] = f1.y;
    w[4] = f2.x; w[5] = f2.y; w[6] = f3.x; w[7] = f3.y;
}

__global__ __launch_bounds__(256) void aa_kernel(const float* __restrict__ aa,
                                                 const float* __restrict__ pb,
                                                 float* __restrict__ out) {
    const int row = blockIdx.x >> 2;           // b*512 + e
    const int seg = blockIdx.x & 3;
    const int t   = threadIdx.x;
    const int o0  = seg * 2048 + t * 8;
    const __half* zr = g_z + (size_t)row * T_;

    float w[24];
    if (o0 >= 8 && o0 + 16 <= T_) {
        uint4 v0 = *(const uint4*)(zr + o0 - 8);
        uint4 v1 = *(const uint4*)(zr + o0);
        uint4 v2 = *(const uint4*)(zr + o0 + 8);
        unp8(v0, w); unp8(v1, w + 8); unp8(v2, w + 16);
    } else {
#pragma unroll
        for (int j = 0; j < 24; j++) {
            int g = o0 - 8 + j;
            w[j] = (g >= 0 && g < T_) ? __half2float(zr[g]) : 0.f;
        }
    }

    float kc[KS];
#pragma unroll
    for (int j = 0; j < KS; j++) kc[j] = __ldg(&aa[j]);
    float bias = __ldg(&pb[row & (D_ - 1)]);

    unsigned long long E[12], O[11], acc[4];
#pragma unroll
    for (int m = 0; m < 12; m++) E[m] = pack2(w[2 * m], w[2 * m + 1]);
#pragma unroll
    for (int m = 0; m < 11; m++) O[m] = pack2(w[2 * m + 1], w[2 * m + 2]);
    unsigned long long b2 = pack2(bias, bias);
#pragma unroll
    for (int p = 0; p < 4; p++) acc[p] = b2;

#pragma unroll
    for (int j = 0; j < KS; j++) {
        unsigned long long k2 = pack2(kc[j], kc[j]);
        const unsigned long long* src = (j & 1) ? &O[j >> 1] : &E[j >> 1];
#pragma unroll
        for (int p = 0; p < 4; p++) acc[p] = fma2(k2, src[p], acc[p]);
    }

    float* op = out + (size_t)row * T_ + o0;
    float2 a0 = unpack2(acc[0]), a1 = unpack2(acc[1]);
    float2 a2 = unpack2(acc[2]), a3 = unpack2(acc[3]);
    float4 v0, v1;
    v0.x = a0.x; v0.y = a0.y; v0.z = a1.x; v0.w = a1.y;
    v1.x = a2.x; v1.y = a2.y; v1.z = a3.x; v1.w = a3.y;
    *(float4*)op       = v0;
    *(float4*)(op + 4) = v1;
}

// ---------------- launch ----------------
extern "C" void kernel_launch(void* const* d_in, const int* in_sizes, int n_in,
                              void* d_out, int out_size) {
    const float* x      = (const float*)d_in[0];
    const float* conv_w = (const float*)d_in[1];
    const float* conv_b = (const float*)d_in[2];
    const float* aa_k   = (const float*)d_in[3];
    const float* proj_w = (const float*)d_in[4];
    const float* proj_b = (const float*)d_in[5];
    float* out = (float*)d_out;

    cudaFuncSetAttribute(gemm_kernel, cudaFuncAttributeMaxDynamicSharedMemorySize, GEMM_SMEM);

    prep_kernel<<<dim3(XPREP_BLKS + FOLD_BLKS + 2), 256>>>(x, conv_w, conv_b, proj_w);
    gemm_kernel<<<dim3(L_ / 128, D_ / 128, B_), 512, GEMM_SMEM>>>();
    aa_kernel<<<dim3(B_ * D_ * 4), 256>>>(aa_k, proj_b, out);
}

// round 7
// speedup vs baseline: 3.5774x; 1.1028x over previous
#include <cuda_runtime.h>
#include <cuda_fp16.h>
#include <cstdint>

#define B_   8
#define D_   512
#define L_   4096
#define LP_  4097
#define T_   8192
#define KS   17

// ---------------- device scratch ----------------
__device__ __half g_A[3][D_][D_];      // folded weights fp16 [k][e][c]
__device__ __half g_X[B_][LP_][D_];    // transposed x fp16 [b][i][c], row L zeroed
__device__ float  g_cb[D_];            // projected conv bias
__device__ __half g_z[(size_t)B_ * D_ * T_];   // intermediate (67 MB, fp16)

// ---------------- PTX helpers ----------------
__device__ __forceinline__ uint32_t smem_u32(const void* p) {
    uint32_t a;
    asm("{ .reg .u64 t; cvta.to.shared.u64 t, %1; cvt.u32.u64 %0, t; }" : "=r"(a) : "l"(p));
    return a;
}
__device__ __forceinline__ void cp16(uint32_t dst, const void* src) {
    asm volatile("cp.async.cg.shared.global [%0], [%1], 16;" :: "r"(dst), "l"(src));
}
#define CP_COMMIT()  asm volatile("cp.async.commit_group;" ::: "memory")
#define CP_WAIT2()   asm volatile("cp.async.wait_group 2;" ::: "memory")

__device__ __forceinline__ void ldsm_x4(uint32_t* r, uint32_t addr) {
    asm volatile("ldmatrix.sync.aligned.m8n8.x4.shared.b16 {%0,%1,%2,%3}, [%4];"
                 : "=r"(r[0]), "=r"(r[1]), "=r"(r[2]), "=r"(r[3]) : "r"(addr));
}
__device__ __forceinline__ void mma_fp16(float* d, const uint32_t* a, const uint32_t* b) {
    asm volatile("mma.sync.aligned.m16n8k16.row.col.f32.f16.f16.f32 "
                 "{%0,%1,%2,%3}, {%4,%5,%6,%7}, {%8,%9}, {%0,%1,%2,%3};"
                 : "+f"(d[0]), "+f"(d[1]), "+f"(d[2]), "+f"(d[3])
                 : "r"(a[0]), "r"(a[1]), "r"(a[2]), "r"(a[3]), "r"(b[0]), "r"(b[1]));
}
__device__ __forceinline__ unsigned long long pack2(float lo, float hi) {
    unsigned long long r;
    asm("mov.b64 %0, {%1, %2};" : "=l"(r) : "f"(lo), "f"(hi));
    return r;
}
__device__ __forceinline__ unsigned long long fma2(unsigned long long a,
                                                   unsigned long long b,
                                                   unsigned long long c) {
    unsigned long long d;
    asm("fma.rn.f32x2 %0, %1, %2, %3;" : "=l"(d) : "l"(a), "l"(b), "l"(c));
    return d;
}
__device__ __forceinline__ float2 unpack2(unsigned long long v) {
    float2 f;
    asm("mov.b64 {%0, %1}, %2;" : "=f"(f.x), "=f"(f.y) : "l"(v));
    return f;
}

// ---------------- kernel 1 (merged prep): fold | cb | xprep -----------------
// blocks [0, 256)      : fold  (tile 32e x 32c x 3k; thread 2e x 2c x 3k)
// blocks [256, 258)    : cb
// blocks [258, 258+4096): xprep (tile 64i x 64c, float4 in / uint4 out)
#define FOLD_BLKS 256
#define CB_BLKS   2
#define XPREP_BLKS 4096
#define PREP_GRID (FOLD_BLKS + CB_BLKS + XPREP_BLKS)

__global__ __launch_bounds__(256, 5) void prep_kernel(const float* __restrict__ x,
                                                      const float* __restrict__ conv_w,
                                                      const float* __restrict__ conv_b,
                                                      const float* __restrict__ proj_w) {
    __shared__ float sm[4192];      // fold: 32*33 + 32*98 ; xprep: 64*65
    const int bx = blockIdx.x;
    const int t  = threadIdx.x;

    if (bx < FOLD_BLKS) {
        // ---- fold ----
        float (*sP)[33] = (float (*)[33])sm;               // [d][e]
        float (*sW)[98] = (float (*)[98])(sm + 32 * 33);   // [d][c*3+k]
        const int c0 = (bx & 15) * 32;
        const int e0 = (bx >> 4) * 32;
        const int tx = t & 15;       // c pair
        const int ty = t >> 4;       // e pair

        float acc[3][2][2];
#pragma unroll
        for (int k = 0; k < 3; k++)
#pragma unroll
            for (int e = 0; e < 2; e++) { acc[k][e][0] = 0.f; acc[k][e][1] = 0.f; }

        for (int d0 = 0; d0 < D_; d0 += 32) {
#pragma unroll
            for (int p = 0; p < 4; p++) {
                int idx = p * 256 + t;
                int e = idx >> 5, d = idx & 31;
                sP[d][e] = proj_w[(size_t)(e0 + e) * D_ + d0 + d];
            }
#pragma unroll
            for (int p = 0; p < 12; p++) {
                int idx = p * 256 + t;
                int d = idx / 96, rem = idx % 96;
                sW[d][rem] = conv_w[(size_t)(d0 + d) * (D_ * 3) + (size_t)c0 * 3 + rem];
            }
            __syncthreads();
#pragma unroll
            for (int dd = 0; dd < 32; dd++) {
                float pe0 = sP[dd][ty * 2 + 0];
                float pe1 = sP[dd][ty * 2 + 1];
#pragma unroll
                for (int c = 0; c < 2; c++)
#pragma unroll
                    for (int k = 0; k < 3; k++) {
                        float w = sW[dd][(tx * 2 + c) * 3 + k];
                        acc[k][0][c] += pe0 * w;
                        acc[k][1][c] += pe1 * w;
                    }
            }
            __syncthreads();
        }
#pragma unroll
        for (int k = 0; k < 3; k++)
#pragma unroll
            for (int e = 0; e < 2; e++)
#pragma unroll
                for (int c = 0; c < 2; c++)
                    g_A[k][e0 + ty * 2 + e][c0 + tx * 2 + c] = __float2half_rn(acc[k][e][c]);
    } else if (bx < FOLD_BLKS + CB_BLKS) {
        // ---- cb ----
        int e = (bx - FOLD_BLKS) * 256 + t;
        if (e < D_) {
            float s = 0.f;
            const float* row = proj_w + (size_t)e * D_;
#pragma unroll 8
            for (int d = 0; d < D_; d++) s += row[d] * conv_b[d];
            g_cb[e] = s;
        }
    } else {
        // ---- xprep: 64i x 64c tile ----
        float* s = sm;               // [c][i], pad 65
        const int bx2 = bx - (FOLD_BLKS + CB_BLKS);
        const int i0 = (bx2 & 63) * 64;
        const int c0 = ((bx2 >> 6) & 7) * 64;
        const int b  = bx2 >> 9;

#pragma unroll
        for (int p = 0; p < 4; p++) {
            int idx = p * 256 + t;
            int c = idx >> 4, q = idx & 15;
            float4 v = *(const float4*)(x + ((size_t)b * D_ + (c0 + c)) * L_ + i0 + q * 4);
            float* d = &s[c * 65 + q * 4];
            d[0] = v.x; d[1] = v.y; d[2] = v.z; d[3] = v.w;
        }
        if (i0 == 0 && t < 32) {
            __half2 z2 = __floats2half2_rn(0.f, 0.f);
            *(__half2*)&g_X[b][L_][c0 + t * 2] = z2;
        }
        __syncthreads();
#pragma unroll
        for (int p = 0; p < 2; p++) {
            int idx = p * 256 + t;
            int i = idx >> 3, c8 = (idx & 7) * 8;
            float w[8];
#pragma unroll
            for (int j = 0; j < 8; j++) w[j] = s[(c8 + j) * 65 + i];
            __half2 h0 = __floats2half2_rn(w[0], w[1]);
            __half2 h1 = __floats2half2_rn(w[2], w[3]);
            __half2 h2 = __floats2half2_rn(w[4], w[5]);
            __half2 h3 = __floats2half2_rn(w[6], w[7]);
            uint4 u;
            u.x = *(uint32_t*)&h0; u.y = *(uint32_t*)&h1;
            u.z = *(uint32_t*)&h2; u.w = *(uint32_t*)&h3;
            *(uint4*)&g_X[b][i0 + i][c0 + c8] = u;
        }
    }
}

// ---------------- kernel 2: single-pass fp16 HMMA GEMM, 3-stage pipeline ----
#define KC      64
#define NCH     (D_ / KC)            // 8
#define ROWB    144
#define A_PLANE (128 * ROWB)         // 18432
#define A_SIZE  (3 * A_PLANE)        // 55296
#define X_ROWS  129
#define X_SIZE  (X_ROWS * ROWB)      // 18576
#define STAGE   (A_SIZE + X_SIZE)    // 73872
#define NSTAGE  3
#define GEMM_SMEM (NSTAGE * STAGE)   // 221616

__device__ __forceinline__ void load_stage(uint32_t sb, int st, int ch,
                                           int e0, int i0, int b, int t) {
    const int c0 = ch * KC;
    const uint32_t base = sb + (uint32_t)st * STAGE;
#pragma unroll
    for (int p = 0; p < 6; p++) {
        int idx = p * 512 + t;
        int plane = idx >> 10;
        int rem = idx & 1023;
        int row = rem >> 3, cb = rem & 7;
        const __half* src = &g_A[plane][0][0] + (size_t)(e0 + row) * D_ + c0 + cb * 8;
        cp16(base + plane * A_PLANE + row * ROWB + cb * 16, src);
    }
    for (int idx = t; idx < X_ROWS * 8; idx += 512) {
        int row = idx >> 3, cb = idx & 7;
        const __half* src = &g_X[b][0][0] + (size_t)(i0 + row) * D_ + c0 + cb * 8;
        cp16(base + A_SIZE + row * ROWB + cb * 16, src);
    }
}

__global__ void __launch_bounds__(512, 1) gemm_kernel() {
    extern __shared__ char smem[];
    const uint32_t sb = smem_u32(smem);
    const int t = threadIdx.x, wid = t >> 5, lane = t & 31;
    const int i0 = blockIdx.x * 128, e0 = blockIdx.y * 128, b = blockIdx.z;
    const int e_w = (wid & 3) * 32;
    const int i_w = (wid >> 2) * 32;

    float accE[2][4][4], accO[2][4][4];
#pragma unroll
    for (int mt = 0; mt < 2; mt++)
#pragma unroll
        for (int nt = 0; nt < 4; nt++)
#pragma unroll
            for (int j = 0; j < 4; j++) { accE[mt][nt][j] = 0.f; accO[mt][nt][j] = 0.f; }

    load_stage(sb, 0, 0, e0, i0, b, t);
    CP_COMMIT();
    load_stage(sb, 1, 1, e0, i0, b, t);
    CP_COMMIT();

    for (int ch = 0; ch < NCH; ++ch) {
        if (ch + 2 < NCH)
            load_stage(sb, (ch + 2) % NSTAGE, ch + 2, e0, i0, b, t);
        CP_COMMIT();
        CP_WAIT2();
        __syncthreads();

        const uint32_t sA = sb + (uint32_t)(ch % NSTAGE) * STAGE;
        const uint32_t sX = sA + A_SIZE;
        const uint32_t aRow = (uint32_t)(e_w + (lane & 15)) * ROWB + (uint32_t)(lane >> 4) * 16;
        const uint32_t xRow = sX + (uint32_t)(i_w + lane) * ROWB;

#pragma unroll
        for (int kh = 0; kh < 4; ++kh) {
            const uint32_t kb = (uint32_t)kh * 32;
            uint32_t bX[4][2], bS[4][2];
            {
                uint32_t r1[4], r2[4];
                ldsm_x4(r1, xRow + kb);
                ldsm_x4(r2, xRow + kb + 16);
#pragma unroll
                for (int nt = 0; nt < 4; nt++) { bX[nt][0] = r1[nt]; bX[nt][1] = r2[nt]; }
                ldsm_x4(r1, xRow + ROWB + kb);
                ldsm_x4(r2, xRow + ROWB + kb + 16);
#pragma unroll
                for (int nt = 0; nt < 4; nt++) { bS[nt][0] = r1[nt]; bS[nt][1] = r2[nt]; }
            }
#pragma unroll
            for (int s = 0; s < 3; ++s) {
                uint32_t aF[2][4];
#pragma unroll
                for (int mt = 0; mt < 2; mt++)
                    ldsm_x4(aF[mt], sA + s * A_PLANE + aRow + mt * (16 * ROWB) + kb);
#pragma unroll
                for (int mt = 0; mt < 2; mt++)
#pragma unroll
                    for (int nt = 0; nt < 4; nt++) {
                        float* d = (s == 1) ? accE[mt][nt] : accO[mt][nt];
                        mma_fp16(d, aF[mt], (s == 2) ? bS[nt] : bX[nt]);
                    }
            }
        }
        __syncthreads();
    }

    // ---- epilogue: interleave even/odd, add folded conv bias, write fp16 z ----
#pragma unroll
    for (int mt = 0; mt < 2; mt++) {
        int r0 = e0 + e_w + mt * 16 + (lane >> 2);
        float cb0 = g_cb[r0], cb1 = g_cb[r0 + 8];
#pragma unroll
        for (int nt = 0; nt < 4; nt++) {
            int ie = i0 + i_w + nt * 8 + (lane & 3) * 2;
            __half2 p0 = __floats2half2_rn(accE[mt][nt][0] + cb0, accO[mt][nt][0] + cb0);
            __half2 p1 = __floats2half2_rn(accE[mt][nt][1] + cb0, accO[mt][nt][1] + cb0);
            __half2 p2 = __floats2half2_rn(accE[mt][nt][2] + cb1, accO[mt][nt][2] + cb1);
            __half2 p3 = __floats2half2_rn(accE[mt][nt][3] + cb1, accO[mt][nt][3] + cb1);
            uint2 u0, u1;
            u0.x = *(uint32_t*)&p0; u0.y = *(uint32_t*)&p1;
            u1.x = *(uint32_t*)&p2; u1.y = *(uint32_t*)&p3;
            *(uint2*)(g_z + ((size_t)(b * D_ + r0)) * T_ + 2 * ie)     = u0;
            *(uint2*)(g_z + ((size_t)(b * D_ + r0 + 8)) * T_ + 2 * ie) = u1;
        }
    }
}

// ---------------- kernel 3: depthwise 17-tap AA, direct-gmem, f32x2 ---------
__device__ __forceinline__ void unp8(uint4 v, float* w) {
    const __half2* h = (const __half2*)&v;
    float2 f0 = __half22float2(h[0]);
    float2 f1 = __half22float2(h[1]);
    float2 f2 = __half22float2(h[2]);
    float2 f3 = __half22float2(h[3]);
    w[0] = f0.x; w[1] = f0.y; w[2] = f1.x; w[3] = f1.y;
    w[4] = f2.x; w[5] = f2.y; w[6] = f3.x; w[7] = f3.y;
}

__global__ __launch_bounds__(256) void aa_kernel(const float* __restrict__ aa,
                                                 const float* __restrict__ pb,
                                                 float* __restrict__ out) {
    const int row = blockIdx.x >> 2;           // b*512 + e
    const int seg = blockIdx.x & 3;
    const int t   = threadIdx.x;
    const int o0  = seg * 2048 + t * 8;
    const __half* zr = g_z + (size_t)row * T_;

    float w[24];
    if (o0 >= 8 && o0 + 16 <= T_) {
        uint4 v0 = *(const uint4*)(zr + o0 - 8);
        uint4 v1 = *(const uint4*)(zr + o0);
        uint4 v2 = *(const uint4*)(zr + o0 + 8);
        unp8(v0, w); unp8(v1, w + 8); unp8(v2, w + 16);
    } else {
#pragma unroll
        for (int j = 0; j < 24; j++) {
            int g = o0 - 8 + j;
            w[j] = (g >= 0 && g < T_) ? __half2float(zr[g]) : 0.f;
        }
    }

    float kc[KS];
#pragma unroll
    for (int j = 0; j < KS; j++) kc[j] = __ldg(&aa[j]);
    float bias = __ldg(&pb[row & (D_ - 1)]);

    unsigned long long E[12], O[11], acc[4];
#pragma unroll
    for (int m = 0; m < 12; m++) E[m] = pack2(w[2 * m], w[2 * m + 1]);
#pragma unroll
    for (int m = 0; m < 11; m++) O[m] = pack2(w[2 * m + 1], w[2 * m + 2]);
    unsigned long long b2 = pack2(bias, bias);
#pragma unroll
    for (int p = 0; p < 4; p++) acc[p] = b2;

#pragma unroll
    for (int j = 0; j < KS; j++) {
        unsigned long long k2 = pack2(kc[j], kc[j]);
        const unsigned long long* src = (j & 1) ? &O[j >> 1] : &E[j >> 1];
#pragma unroll
        for (int p = 0; p < 4; p++) acc[p] = fma2(k2, src[p], acc[p]);
    }

    float* op = out + (size_t)row * T_ + o0;
    float2 a0 = unpack2(acc[0]), a1 = unpack2(acc[1]);
    float2 a2 = unpack2(acc[2]), a3 = unpack2(acc[3]);
    float4 v0, v1;
    v0.x = a0.x; v0.y = a0.y; v0.z = a1.x; v0.w = a1.y;
    v1.x = a2.x; v1.y = a2.y; v1.z = a3.x; v1.w = a3.y;
    *(float4*)op       = v0;
    *(float4*)(op + 4) = v1;
}

// ---------------- launch ----------------
extern "C" void kernel_launch(void* const* d_in, const int* in_sizes, int n_in,
                              void* d_out, int out_size) {
    const float* x      = (const float*)d_in[0];
    const float* conv_w = (const float*)d_in[1];
    const float* conv_b = (const float*)d_in[2];
    const float* aa_k   = (const float*)d_in[3];
    const float* proj_w = (const float*)d_in[4];
    const float* proj_b = (const float*)d_in[5];
    float* out = (float*)d_out;

    cudaFuncSetAttribute(gemm_kernel, cudaFuncAttributeMaxDynamicSharedMemorySize, GEMM_SMEM);

    prep_kernel<<<dim3(PREP_GRID), 256>>>(x, conv_w, conv_b, proj_w);
    gemm_kernel<<<dim3(L_ / 128, D_ / 128, B_), 512, GEMM_SMEM>>>();
    aa_kernel<<<dim3(B_ * D_ * 4), 256>>>(aa_k, proj_b, out);
}